// round 8
// baseline (speedup 1.0000x reference)
#include <cuda_runtime.h>

// WinCorr: out[s=(i,j,k), d,h,w] = scale * sum_c fixed[c,d,h,w] * moving[c, d+i-1, h+j-1, w+k-1]
// fixed/moving (1,32,96,96,96) f32; out (1,27,96,96,96) f32; zero padding.
// s = i*9 + j*3 + k.  Pass p handles i=p (one moving d-plane per pass-channel).

#define CC   32
#define DD   96
#define HH   96
#define WW   96
#define HWSZ (HH * WW)
#define DHW  (DD * HWSZ)

#define RW      40                 // smem row width, words (160B; covers gw in [w0-4, w0+36))
#define SROWS   6                  // rows per warp stage: gh in [hbase-1, hbase+4]
#define STAGE_W (SROWS * RW)       // 240 words = 960B
#define NSTAGE  4
#define WARP_W  (NSTAGE * STAGE_W) // 960 words per warp
#define NIT     (3 * CC)           // 96 flat iterations
#define QPR     10                 // 16B chunks per row
#define OPS     (SROWS * QPR)      // 60 cp.async ops per warp-stage

__device__ __forceinline__ void cp_async16(unsigned s, const void* g) {
    asm volatile("cp.async.cg.shared.global [%0], [%1], 16;\n" :: "r"(s), "l"(g));
}
__device__ __forceinline__ void cp_commit() {
    asm volatile("cp.async.commit_group;\n" ::: "memory");
}
__device__ __forceinline__ void cp_wait3() {
    asm volatile("cp.async.wait_group 3;\n" ::: "memory");
}

__global__ __launch_bounds__(256, 3)
void wincorr_kernel(const float* __restrict__ fx,
                    const float* __restrict__ mv,
                    float* __restrict__ out)
{
    __shared__ float sm[8 * WARP_W];   // 8 warps x 4 stages x 960B = 30720B

    const int tx  = threadIdx.x;       // lane -> w
    const int ty  = threadIdx.y;       // warp -> 4-row h strip
    const int tid = ty * 32 + tx;

    const int w0 = blockIdx.x * 32;
    const int h0 = blockIdx.y * 32;
    const int d  = blockIdx.z;

    const int hbase = h0 + 4 * ty;     // this thread owns h = hbase..hbase+3
    const int w = w0 + tx;

    // pre-zero all smem once (halo slots stay zero forever; cross-thread -> one barrier)
    #pragma unroll
    for (int i = tid; i < 8 * WARP_W; i += 256) sm[i] = 0.f;

    // per-thread c/p-invariant cp.async descriptors (2 chunk-ops per lane)
    int      po[2];   // word offset within a d-plane
    unsigned db[2];   // byte offset within a stage
    bool     ok[2];
    #pragma unroll
    for (int t = 0; t < 2; ++t) {
        int o  = tx + 32 * t;
        int r  = o / QPR;
        int q  = o - r * QPR;
        int gh = hbase - 1 + r;
        int gs = w0 - 4 + 4 * q;
        ok[t] = (o < OPS) && ((unsigned)gh < HH) && (gs >= 0) && (gs + 4 <= WW);
        po[t] = ok[t] ? (gh * WW + gs) : 0;
        db[t] = (unsigned)(r * (RW * 4) + q * 16);
    }

    __syncthreads();   // zeros (written block-strided) visible before any cp.async lands

    const unsigned wsmb = (unsigned)__cvta_generic_to_shared(sm) + ty * (WARP_W * 4);
    const char* mvb = (const char*)mv;

    // ---- prologue: launch groups for it = 0,1,2 ----
    #pragma unroll
    for (int jt = 0; jt < 3; ++jt) {
        int gd = d + (jt >> 5) - 1;                 // pass of jt (0 here) -> gd = d-1
        if ((unsigned)gd < DD) {
            const char* pb = mvb + ((size_t)(jt & 31) * DHW + (size_t)gd * HWSZ) * 4;
            unsigned sb = wsmb + (unsigned)(jt & 3) * (STAGE_W * 4);
            if (ok[0]) cp_async16(sb + db[0], pb + (size_t)po[0] * 4);
            if (ok[1]) cp_async16(sb + db[1], pb + (size_t)po[1] * 4);
        }
        cp_commit();
    }

    const float* fbase = fx + (size_t)d * HWSZ + (size_t)hbase * WW + w;
    float fc[4];
    fc[0] = __ldg(fbase);
    fc[1] = __ldg(fbase + WW);
    fc[2] = __ldg(fbase + 2 * WW);
    fc[3] = __ldg(fbase + 3 * WW);

    float acc[36];
    #pragma unroll
    for (int s = 0; s < 36; ++s) acc[s] = 0.f;

    float* obase = out + (size_t)d * HWSZ + (size_t)hbase * WW + w;
    const float scale = 0.17677669529663687f;   // 32^-0.5

    for (int it = 0; it < NIT; ++it) {
        // launch group it+3 (stage (it-1)&3, finished last iteration)
        const int jt = it + 3;
        if (jt < NIT) {
            int gd = d + (jt >> 5) - 1;
            if ((unsigned)gd < DD) {
                const char* pb = mvb + ((size_t)(jt & 31) * DHW + (size_t)gd * HWSZ) * 4;
                unsigned sb = wsmb + (unsigned)(jt & 3) * (STAGE_W * 4);
                if (ok[0]) cp_async16(sb + db[0], pb + (size_t)po[0] * 4);
                if (ok[1]) cp_async16(sb + db[1], pb + (size_t)po[1] * 4);
            }
        }
        cp_commit();
        cp_wait3();        // group `it` complete; it+1..it+3 may still fly
        __syncwarp();      // cross-lane visibility of this warp's stage

        const float f0 = fc[0], f1 = fc[1], f2 = fc[2], f3 = fc[3];
        if (it + 1 < NIT) {   // prefetch fixed for next iteration (fixed is pass-invariant)
            const float* fp = fbase + (size_t)((it + 1) & 31) * DHW;
            fc[0] = __ldg(fp);
            fc[1] = __ldg(fp + WW);
            fc[2] = __ldg(fp + 2 * WW);
            fc[3] = __ldg(fp + 3 * WW);
        }

        // skip compute if this pass's moving plane is fully OOB (acc stays 0)
        const int gdc = d + (it >> 5) - 1;
        if ((unsigned)gdc < DD) {
            const float* buf = sm + ty * WARP_W + (it & 3) * STAGE_W + tx + 3;
            // rows r=0..5 (gh = hbase-1+r); out row lo: jj = r-lo in [0,2]
            #pragma unroll
            for (int r = 0; r < SROWS; ++r) {
                #pragma unroll
                for (int kk = 0; kk < 3; ++kk) {
                    const float m = buf[r * RW + kk];
                    if (r <= 2)            acc[0 * 9 + (r    ) * 3 + kk] += f0 * m;
                    if (r >= 1 && r <= 3)  acc[1 * 9 + (r - 1) * 3 + kk] += f1 * m;
                    if (r >= 2 && r <= 4)  acc[2 * 9 + (r - 2) * 3 + kk] += f2 * m;
                    if (r >= 3)            acc[3 * 9 + (r - 3) * 3 + kk] += f3 * m;
                }
            }
        }

        // end of pass: write 9 shift-planes x 4 rows, reset accumulators
        if ((it & 31) == 31) {
            const int p = it >> 5;
            float* ob = obase + (size_t)(p * 9) * DHW;
            #pragma unroll
            for (int j = 0; j < 9; ++j) {
                #pragma unroll
                for (int lo = 0; lo < 4; ++lo)
                    ob[(size_t)j * DHW + lo * WW] = acc[lo * 9 + j] * scale;
            }
            #pragma unroll
            for (int s = 0; s < 36; ++s) acc[s] = 0.f;
        }
    }
}

extern "C" void kernel_launch(void* const* d_in, const int* in_sizes, int n_in,
                              void* d_out, int out_size)
{
    const float* fixed  = (const float*)d_in[0];
    const float* moving = (const float*)d_in[1];
    float* out = (float*)d_out;

    dim3 block(32, 8, 1);
    dim3 grid(WW / 32, HH / 32, DD);   // (3, 3, 96) = 864 blocks
    wincorr_kernel<<<grid, block>>>(fixed, moving, out);
}

// round 9
// speedup vs baseline: 1.0761x; 1.0761x over previous
#include <cuda_runtime.h>

// WinCorr: out[s=(i,j,k), d,h,w] = scale * sum_c fixed[c,d,h,w] * moving[c, d+i-1, h+j-1, w+k-1]
// fixed/moving (1,32,96,96,96) f32; out (1,27,96,96,96) f32; zero padding.

#define CC   32
#define DD   96
#define HH   96
#define WW   96
#define HWSZ (HH * WW)
#define DHW  (DD * HWSZ)

#define RW      40                  // smem row width in words (160B; gw in [w0-4, w0+36))
#define TROWS   12                  // 3 dz * 4 h-rows (gh in [h-1, h+2])
#define STAGE_W (TROWS * RW)        // 480 words = 1920B per warp-stage
#define NSTAGE  3
#define WARP_W  (NSTAGE * STAGE_W)  // 1440 words = 5760B per warp
#define QPR     10                  // 16B chunks per row
#define OPS     (TROWS * QPR)       // 120 cp.async ops per warp-stage
#define NOPS    4                   // ceil(120/32) per lane

__device__ __forceinline__ void cp_async16(unsigned s, const void* g) {
    asm volatile("cp.async.cg.shared.global [%0], [%1], 16;\n" :: "r"(s), "l"(g));
}
__device__ __forceinline__ void cp_commit() {
    asm volatile("cp.async.commit_group;\n" ::: "memory");
}
__device__ __forceinline__ void cp_wait2() {
    asm volatile("cp.async.wait_group 2;\n" ::: "memory");
}

__global__ __launch_bounds__(256, 3)
void wincorr_kernel(const float* __restrict__ fx,
                    const float* __restrict__ mv,
                    float* __restrict__ out)
{
    __shared__ float sm[8 * WARP_W];   // 8 warps * 5760B = 46080B

    const int tx  = threadIdx.x;       // lane -> w
    const int ty  = threadIdx.y;       // warp -> 2-row h strip
    const int tid = ty * 32 + tx;

    const int w0 = blockIdx.x * 32;
    const int h0 = blockIdx.y * 16;
    const int d  = blockIdx.z;

    const int h = h0 + 2 * ty;         // outputs (d,h,w), (d,h+1,w)
    const int w = w0 + tx;

    // pre-zero all smem once: OOB slots (d/h/w halo) stay zero for the whole kernel
    #pragma unroll
    for (int i = tid; i < 8 * WARP_W; i += 256) sm[i] = 0.f;

    // ---- per-lane c-invariant cp.async descriptors ----
    int      srcB[NOPS];   // byte offset into a channel of moving; -1 = skip
    unsigned db[NOPS];     // byte offset within a stage
    #pragma unroll
    for (int t = 0; t < NOPS; ++t) {
        int o  = tx + 32 * t;
        int r  = o / QPR;              // row 0..11
        int q  = o - r * QPR;          // chunk 0..9
        int dz = r >> 2;
        int rr = r & 3;
        int gd = d + dz - 1;
        int gh = h - 1 + rr;
        int gs = w0 - 4 + 4 * q;
        bool v = (o < OPS) && ((unsigned)gd < DD) && ((unsigned)gh < HH)
                           && (gs >= 0) && (gs + 4 <= WW);
        srcB[t] = v ? (gd * HWSZ + gh * WW + gs) * 4 : -1;
        db[t]   = (unsigned)(r * (RW * 4) + q * 16);
    }

    __syncthreads();   // zeros visible before any cp.async lands (only barrier in kernel)

    const unsigned wsmb = (unsigned)__cvta_generic_to_shared(sm) + ty * (WARP_W * 4);
    const char* mvb = (const char*)mv;

    // ---- prologue: launch channel 0 and 1 tiles ----
    #pragma unroll
    for (int c = 0; c < 2; ++c) {
        const unsigned sb = wsmb + (unsigned)(c % NSTAGE) * (STAGE_W * 4);
        const char* pb = mvb + (size_t)c * (DHW * 4);
        #pragma unroll
        for (int t = 0; t < NOPS; ++t)
            if (srcB[t] >= 0) cp_async16(sb + db[t], pb + srcB[t]);
        cp_commit();
    }

    const float* fp = fx + (size_t)d * HWSZ + (size_t)h * WW + w;
    float fa = __ldg(fp);
    float fb = __ldg(fp + WW);

    float acc0[27], acc1[27];
    #pragma unroll
    for (int s = 0; s < 27; ++s) { acc0[s] = 0.f; acc1[s] = 0.f; }

    for (int c = 0; c < CC; ++c) {
        // launch channel c+2 into stage (c+2)%3 (its previous user, channel c-1, is done)
        const int jt = c + 2;
        if (jt < CC) {
            const unsigned sb = wsmb + (unsigned)(jt % NSTAGE) * (STAGE_W * 4);
            const char* pb = mvb + (size_t)jt * (DHW * 4);
            #pragma unroll
            for (int t = 0; t < NOPS; ++t)
                if (srcB[t] >= 0) cp_async16(sb + db[t], pb + srcB[t]);
        }
        cp_commit();
        cp_wait2();        // group c complete; c+1, c+2 still in flight
        __syncwarp();      // cross-lane visibility within this warp

        const float f0 = fa, f1 = fb;
        if (c + 1 < CC) {
            fa = __ldg(fp + (size_t)(c + 1) * DHW);
            fb = __ldg(fp + (size_t)(c + 1) * DHW + WW);
        }

        // ---- 36 conflict-free LDS [R+imm] + 54 FFMA ----
        const float* buf = sm + ty * WARP_W + (c % NSTAGE) * STAGE_W + tx + 3;
        #pragma unroll
        for (int dz = 0; dz < 3; ++dz) {
            #pragma unroll
            for (int rr = 0; rr < 4; ++rr) {       // gh = h-1 .. h+2
                #pragma unroll
                for (int kk = 0; kk < 3; ++kk) {
                    const float m = buf[(dz * 4 + rr) * RW + kk];
                    if (rr < 3) acc0[dz * 9 + rr * 3 + kk]       += f0 * m;
                    if (rr > 0) acc1[dz * 9 + (rr - 1) * 3 + kk] += f1 * m;
                }
            }
        }
    }

    const float scale = 0.17677669529663687f;   // 32^-0.5
    float* op = out + (size_t)d * HWSZ + (size_t)h * WW + w;
    #pragma unroll
    for (int s = 0; s < 27; ++s) {
        op[(size_t)s * DHW]      = acc0[s] * scale;
        op[(size_t)s * DHW + WW] = acc1[s] * scale;
    }
}

extern "C" void kernel_launch(void* const* d_in, const int* in_sizes, int n_in,
                              void* d_out, int out_size)
{
    const float* fixed  = (const float*)d_in[0];
    const float* moving = (const float*)d_in[1];
    float* out = (float*)d_out;

    dim3 block(32, 8, 1);
    dim3 grid(WW / 32, HH / 16, DD);   // (3, 6, 96) = 1728 blocks
    wincorr_kernel<<<grid, block>>>(fixed, moving, out);
}

// round 11
// speedup vs baseline: 1.4952x; 1.3895x over previous
#include <cuda_runtime.h>

// WinCorr: out[s=(i,j,k), d,h,w] = scale * sum_c fixed[c,d,h,w] * moving[c, d+i-1, h+j-1, w+k-1]
// fixed/moving (1,32,96,96,96) f32; out (1,27,96,96,96) f32; zero padding.

#define CC   32
#define DD   96
#define HH   96
#define WW   96
#define HWSZ (HH * WW)
#define DHW  (DD * HWSZ)

#define WT   32
#define HT   16                // 4 warps x 4 h-rows
#define SM_D 3
#define SM_H (HT + 2)          // 18
#define ROWS (SM_D * SM_H)     // 54
#define RW   40                // row width words (160B; gw in [w0-4, w0+36))
#define TILE_W (ROWS * RW)     // 2160 words
#define TILE_B (TILE_W * 4)    // 8640 bytes
#define NSTAGE 4
#define QPR  10                // 16B chunks per row
#define TOTOPS (ROWS * QPR)    // 540
#define NOPS 5                 // ceil(540/128)
#define NTHR 128

__device__ __forceinline__ void cp_async16(unsigned s, const void* g) {
    asm volatile("cp.async.cg.shared.global [%0], [%1], 16;\n" :: "r"(s), "l"(g));
}
__device__ __forceinline__ void cp_commit() {
    asm volatile("cp.async.commit_group;\n" ::: "memory");
}
__device__ __forceinline__ void cp_wait2() {
    asm volatile("cp.async.wait_group 2;\n" ::: "memory");
}

__global__ __launch_bounds__(NTHR, 3)
void wincorr_kernel(const float* __restrict__ fx,
                    const float* __restrict__ mv,
                    float* __restrict__ out)
{
    __shared__ float sm[NSTAGE * TILE_W];   // 34560 B

    const int tx  = threadIdx.x;            // lane -> w
    const int ty  = threadIdx.y;            // warp 0..3 -> 4-row h strip
    const int tid = ty * 32 + tx;

    const int w0 = blockIdx.x * WT;
    const int h0 = blockIdx.y * HT;
    const int d  = blockIdx.z;

    const int h = h0 + 4 * ty;              // outputs h..h+3
    const int w = w0 + tx;

    // pre-zero all stages once: OOB halo slots stay zero for the whole kernel
    for (int i = tid; i < NSTAGE * TILE_W; i += NTHR) sm[i] = 0.f;

    // ---- per-thread c-invariant cp.async descriptors ----
    int      srcB[NOPS];   // byte offset within a moving channel; -1 = skip
    unsigned db[NOPS];     // byte offset within a stage
    #pragma unroll
    for (int t = 0; t < NOPS; ++t) {
        int o  = tid + NTHR * t;
        int r  = o / QPR;                   // tile row 0..53
        int q  = o - r * QPR;               // chunk 0..9
        int dz = r / SM_H;
        int lh = r - dz * SM_H;
        int gd = d  + dz - 1;
        int gh = h0 + lh - 1;
        int gs = w0 - 4 + 4 * q;
        bool v = (o < TOTOPS) && ((unsigned)gd < DD) && ((unsigned)gh < HH)
                              && (gs >= 0) && (gs + 4 <= WW);
        srcB[t] = v ? (gd * HWSZ + gh * WW + gs) * 4 : -1;
        db[t]   = (unsigned)(r * (RW * 4) + q * 16);
    }

    __syncthreads();   // zeros visible before any cp.async lands

    const unsigned smb = (unsigned)__cvta_generic_to_shared(sm);
    const char* mvb = (const char*)mv;

    // ---- prologue: launch channels 0..2 ----
    #pragma unroll
    for (int c = 0; c < 3; ++c) {
        const unsigned sb = smb + (unsigned)(c & (NSTAGE - 1)) * TILE_B;
        const char* pb = mvb + (size_t)c * (DHW * 4);
        #pragma unroll
        for (int t = 0; t < NOPS; ++t)
            if (srcB[t] >= 0) cp_async16(sb + db[t], pb + srcB[t]);
        cp_commit();
    }

    const float* fp = fx + (size_t)d * HWSZ + (size_t)h * WW + w;
    float fc[4];
    fc[0] = __ldg(fp);
    fc[1] = __ldg(fp + WW);
    fc[2] = __ldg(fp + 2 * WW);
    fc[3] = __ldg(fp + 3 * WW);

    float acc[108];                         // [lo][dz*9 + jj*3 + kk]
    #pragma unroll
    for (int s = 0; s < 108; ++s) acc[s] = 0.f;

    #pragma unroll 4
    for (int c = 0; c < CC; ++c) {
        cp_wait2();        // group c complete (c+1, c+2 still in flight)
        __syncthreads();   // ALL warps see tile c AND are done reading stage (c-1)&3

        // now safe: launch channel c+3 into stage (c+3)&3 == (c-1)&3
        const int jt = c + 3;
        if (jt < CC) {
            const unsigned sb = smb + (unsigned)(jt & (NSTAGE - 1)) * TILE_B;
            const char* pb = mvb + (size_t)jt * (DHW * 4);
            #pragma unroll
            for (int t = 0; t < NOPS; ++t)
                if (srcB[t] >= 0) cp_async16(sb + db[t], pb + srcB[t]);
        }
        cp_commit();       // unconditional: keeps group count uniform for wait_group 2

        const float f0 = fc[0], f1 = fc[1], f2 = fc[2], f3 = fc[3];
        if (c + 1 < CC) {
            const float* fn = fp + (size_t)(c + 1) * DHW;
            fc[0] = __ldg(fn);
            fc[1] = __ldg(fn + WW);
            fc[2] = __ldg(fn + 2 * WW);
            fc[3] = __ldg(fn + 3 * WW);
        }

        // ---- 54 conflict-free LDS [R+imm] + 108 FFMA ----
        // rows yy=0..5 -> gh = h-1+yy ; output lo uses jj = yy-lo in [0,2]
        const float* base = sm + (c & (NSTAGE - 1)) * TILE_W + (4 * ty) * RW + tx + 3;
        #pragma unroll
        for (int dz = 0; dz < 3; ++dz) {
            #pragma unroll
            for (int yy = 0; yy < 6; ++yy) {
                #pragma unroll
                for (int kk = 0; kk < 3; ++kk) {
                    const float m = base[(dz * SM_H + yy) * RW + kk];
                    if (yy <= 2)            acc[0 * 27 + dz * 9 + (yy    ) * 3 + kk] += f0 * m;
                    if (yy >= 1 && yy <= 3) acc[1 * 27 + dz * 9 + (yy - 1) * 3 + kk] += f1 * m;
                    if (yy >= 2 && yy <= 4) acc[2 * 27 + dz * 9 + (yy - 2) * 3 + kk] += f2 * m;
                    if (yy >= 3)            acc[3 * 27 + dz * 9 + (yy - 3) * 3 + kk] += f3 * m;
                }
            }
        }
    }

    const float scale = 0.17677669529663687f;   // 32^-0.5
    float* op = out + (size_t)d * HWSZ + (size_t)h * WW + w;
    #pragma unroll
    for (int s = 0; s < 27; ++s) {
        #pragma unroll
        for (int lo = 0; lo < 4; ++lo)
            op[(size_t)s * DHW + lo * WW] = acc[lo * 27 + s] * scale;
    }
}

extern "C" void kernel_launch(void* const* d_in, const int* in_sizes, int n_in,
                              void* d_out, int out_size)
{
    const float* fixed  = (const float*)d_in[0];
    const float* moving = (const float*)d_in[1];
    float* out = (float*)d_out;

    dim3 block(32, 4, 1);                    // 128 threads
    dim3 grid(WW / WT, HH / HT, DD);         // (3, 6, 96) = 1728 blocks
    wincorr_kernel<<<grid, block>>>(fixed, moving, out);
}